// round 2
// baseline (speedup 1.0000x reference)
#include <cuda_runtime.h>
#include <stdint.h>

#define RNODES 256
#define LUT_WORDS 8192        // 2^18 / 32
#define NSTEP 512
#define NSAMP 512
#define NIN 32
#define NOUT 10
// SMEM: col table 32768 + xwords 2048 + rbuf 64 + bits 1024 = 35904 u32
#define SMEM_BYTES (35904 * 4)

// Static device scratch (allocation-free rule).
__device__ uint32_t g_lutbits[RNODES * LUT_WORDS];  // 8 MB bit-packed LUT
__device__ uint32_t g_colPair[RNODES * 128];        // [k][t]: p[k]*W[t,k] | (p[k]*W[t+128,k])<<16
__device__ uint32_t g_xpack[NSAMP * NSTEP];         // per (m,s): 32 input bits
__device__ int      g_inv[RNODES];                  // node -> input slot, or -1
__device__ int      g_init[RNODES];                 // initial state bits
__device__ int      g_mode;                         // bool encoding: 0=int32 1=uint8 2=float32

__device__ __forceinline__ int read_bool(const void* p, long i, int mode) {
    if (mode == 0) return ((const int*)p)[i] != 0;
    if (mode == 1) return ((const unsigned char*)p)[i] != 0;
    return ((const float*)p)[i] != 0.0f;
}

__global__ void detect_kernel(const uint32_t* __restrict__ xw) {
    if (threadIdx.x == 0 && blockIdx.x == 0) {
        int mode = 0;
        for (int i = 0; i < 1024; i++) {
            uint32_t v = xw[i];
            if (v == 0x3f800000u) { mode = 2; break; }  // float32 1.0
            if (v > 1u) mode = 1;                       // packed uint8 bytes
        }
        g_mode = mode;
    }
}

__global__ void pack_lut_kernel(const int* __restrict__ lut) {
    int w = blockIdx.x * blockDim.x + threadIdx.x;
    if (w >= RNODES * LUT_WORDS) return;
    const int* src = lut + (size_t)w * 32;
    uint32_t v = 0;
#pragma unroll
    for (int b = 0; b < 32; b++) v |= ((uint32_t)(src[b] & 1)) << b;
    g_lutbits[w] = v;
}

__global__ void pack_x_kernel(const void* __restrict__ x) {
    int w = blockIdx.x * blockDim.x + threadIdx.x;   // (m*NSTEP + s)
    if (w >= NSAMP * NSTEP) return;
    int mode = g_mode;
    long base = (long)w * 32;
    uint32_t v = 0;
#pragma unroll
    for (int q = 0; q < 32; q++)
        v |= ((uint32_t)read_bool(x, base + q, mode)) << q;
    g_xpack[w] = v;
}

__global__ void prep_kernel(const void* __restrict__ W,
                            const int* __restrict__ primes,
                            const int* __restrict__ input_nodes,
                            const void* __restrict__ init_res) {
    int i = blockIdx.x * blockDim.x + threadIdx.x;
    int mode = g_mode;
    if (i < RNODES) {
        int inv = -1;
#pragma unroll
        for (int q = 0; q < NIN; q++)
            if (input_nodes[q] == i) inv = q;
        g_inv[i] = inv;
        g_init[i] = read_bool(init_res, i, mode);
    }
    if (i >= RNODES * 128) return;
    int k = i >> 7;
    int t = i & 127;
    uint32_t p  = (uint32_t)primes[k];
    uint32_t lo = read_bool(W, (long)t * RNODES + k, mode)          ? p : 0u;
    uint32_t hi = read_bool(W, (long)(t + 128) * RNODES + k, mode)  ? p : 0u;
    g_colPair[i] = lo | (hi << 16);
}

// 128 CTAs x 512 threads. CTA handles 4 samples; 128 threads per sample;
// thread t owns nodes t and t+128 (packed u16 accumulation via __vadd2).
__global__ void __launch_bounds__(512, 1)
reservoir_kernel(const float* __restrict__ roW,
                 const float* __restrict__ rob,
                 float* __restrict__ out) {
    extern __shared__ uint32_t sm[];
    uint32_t* sh_col  = sm;                       // 32768 u32 (128 KB) column table
    uint32_t* sh_xw   = sm + 32768;               // 2048 u32: packed input, 4 samples
    uint32_t* sh_r    = sm + 34816;               // 64 u32: 2 bufs * 4 samples * 8 words
    float*    sh_bits = (float*)(sm + 34880);     // 1024 floats: final states

    const int tid = threadIdx.x;
    const int sid = tid >> 7;        // sample within CTA (0..3)
    const int t   = tid & 127;       // node pair index
    const int ws  = (tid >> 5) & 3;  // warp within sample

    for (int i = tid; i < RNODES * 128; i += 512)
        sh_col[i] = g_colPair[i];
    for (int i = tid; i < 2048; i += 512)
        sh_xw[i] = g_xpack[blockIdx.x * 2048 + i];

    const int inv_lo = g_inv[t];
    const int inv_hi = g_inv[t + 128];
    unsigned b_lo = (unsigned)g_init[t];
    unsigned b_hi = (unsigned)g_init[t + 128];

    __syncthreads();

    const uint32_t* xs = sh_xw + sid * NSTEP;

    for (int s = 0; s < NSTEP; s++) {
        // 1) input override (before the matvec, matching the reference)
        uint32_t xw = xs[s];                        // broadcast LDS
        unsigned a_lo = (inv_lo >= 0) ? ((xw >> inv_lo) & 1u) : b_lo;
        unsigned a_hi = (inv_hi >= 0) ? ((xw >> inv_hi) & 1u) : b_hi;

        // 2) build state bitmask words (double-buffered => one barrier/step)
        unsigned mlo = __ballot_sync(0xffffffffu, a_lo);
        unsigned mhi = __ballot_sync(0xffffffffu, a_hi);
        uint32_t* rbuf = sh_r + ((s & 1) * 32) + sid * 8;
        if ((tid & 31) == 0) {
            rbuf[ws]     = mlo;   // nodes [32ws, 32ws+32)
            rbuf[ws + 4] = mhi;   // nodes [128+32ws, ...)
        }
        __syncthreads();

        uint4 ra = *(const uint4*)(rbuf);
        uint4 rb = *(const uint4*)(rbuf + 4);
        uint32_t wv[8] = {ra.x, ra.y, ra.z, ra.w, rb.x, rb.y, rb.z, rb.w};

        // 3) masked prime sums: idx[t] = sum over set state bits k of colPair[k][t]
        uint32_t idx_lo = 0, idx_hi = 0;
#pragma unroll
        for (int wi = 0; wi < 8; wi++) {
            unsigned mm = wv[wi];          // uniform across warp -> no divergence
            uint32_t acc = 0;              // packed u16 pair (max per word < 65536)
            const uint32_t* colw = sh_col + (wi << 12) + t;
            while (mm) {
                int b = __ffs(mm) - 1;
                mm &= mm - 1;
                acc = __vadd2(acc, colw[b << 7]);
            }
            idx_lo += acc & 0xFFFFu;
            idx_hi += acc >> 16;
        }

        // 4) bit-packed LUT gather (8 MB table, L2-resident)
        uint32_t wlo = g_lutbits[((uint32_t)t << 13) + (idx_lo >> 5)];
        uint32_t whi = g_lutbits[((uint32_t)(t + 128) << 13) + (idx_hi >> 5)];
        b_lo = (wlo >> (idx_lo & 31u)) & 1u;
        b_hi = (whi >> (idx_hi & 31u)) & 1u;
    }

    // Readout: out[m, o] = sum_j rf[m,j] * roW[o,j] + rob[o]
    sh_bits[sid * 256 + t]       = (float)b_lo;
    sh_bits[sid * 256 + t + 128] = (float)b_hi;
    __syncthreads();

    if (t < NOUT) {
        float acc = rob[t];
        const float* wrow = roW + t * RNODES;
        const float* bits = sh_bits + sid * 256;
#pragma unroll 8
        for (int j = 0; j < RNODES; j++)
            acc += bits[j] * wrow[j];
        out[(blockIdx.x * 4 + sid) * NOUT + t] = acc;
    }
}

extern "C" void kernel_launch(void* const* d_in, const int* in_sizes, int n_in,
                              void* d_out, int out_size) {
    const void* x       = d_in[0];                   // bool [512,512,4,8] (dtype-detected)
    const int*  innod   = (const int*)d_in[1];       // int32 [32]
    const int*  lut     = (const int*)d_in[2];       // int32 [256, 262144]
    const void* W       = d_in[3];                   // bool [256,256]
    const int*  primes  = (const int*)d_in[4];       // int32 [256]
    const void* initres = d_in[5];                   // bool [256]
    const float* roW    = (const float*)d_in[6];     // f32 [10,256]
    const float* rob    = (const float*)d_in[7];     // f32 [10]
    float* out = (float*)d_out;                      // f32 [512,10]

    cudaFuncSetAttribute(reservoir_kernel,
                         cudaFuncAttributeMaxDynamicSharedMemorySize, SMEM_BYTES);

    detect_kernel<<<1, 32>>>((const uint32_t*)x);
    pack_lut_kernel<<<(RNODES * LUT_WORDS + 255) / 256, 256>>>(lut);
    pack_x_kernel<<<(NSAMP * NSTEP + 255) / 256, 256>>>(x);
    prep_kernel<<<(RNODES * 128 + 255) / 256, 256>>>(W, primes, innod, initres);
    reservoir_kernel<<<128, 512, SMEM_BYTES>>>(roW, rob, out);
}

// round 3
// speedup vs baseline: 2.6437x; 2.6437x over previous
#include <cuda_runtime.h>
#include <stdint.h>

#define RNODES 256
#define LUT_WORDS 8192        // 2^18 / 32
#define NSTEP 512
#define NSAMP 512
#define NIN 32
#define NOUT 10
#define NGROUP 128            // 2-bit groups of k
// SMEM u32 layout: xw 2048 | rbuf 64 | bits 1024 | tab 49152  = 52288 u32
#define SMEM_U32 52288
#define SMEM_BYTES (SMEM_U32 * 4)   // 209,152 B

// Static device scratch (allocation-free rule).
__device__ uint32_t g_lutbits[RNODES * LUT_WORDS];  // 8 MB bit-packed LUT
__device__ uint2    g_tab[NGROUP * 3 * 64];         // pair-group combo table
__device__ uint32_t g_xpack[NSAMP * NSTEP];         // per (m,s): 32 input bits
__device__ int      g_inv[RNODES];                  // node -> input slot, or -1
__device__ int      g_init[RNODES];                 // initial state bits
__device__ int      g_mode;                         // bool enc: 0=int32 1=uint8 2=float32

__device__ __forceinline__ int read_bool(const void* p, long i, int mode) {
    if (mode == 0) return ((const int*)p)[i] != 0;
    if (mode == 1) return ((const unsigned char*)p)[i] != 0;
    return ((const float*)p)[i] != 0.0f;
}

__global__ void detect_kernel(const uint32_t* __restrict__ xw) {
    if (threadIdx.x == 0 && blockIdx.x == 0) {
        int mode = 0;
        for (int i = 0; i < 1024; i++) {
            uint32_t v = xw[i];
            if (v == 0x3f800000u) { mode = 2; break; }
            if (v > 1u) mode = 1;
        }
        g_mode = mode;
    }
}

__global__ void pack_lut_kernel(const int* __restrict__ lut) {
    int w = blockIdx.x * blockDim.x + threadIdx.x;
    if (w >= RNODES * LUT_WORDS) return;
    const int* src = lut + (size_t)w * 32;
    uint32_t v = 0;
#pragma unroll
    for (int b = 0; b < 32; b++) v |= ((uint32_t)(src[b] & 1)) << b;
    g_lutbits[w] = v;
}

__global__ void pack_x_kernel(const void* __restrict__ x) {
    int w = blockIdx.x * blockDim.x + threadIdx.x;   // (m*NSTEP + s)
    if (w >= NSAMP * NSTEP) return;
    int mode = g_mode;
    long base = (long)w * 32;
    uint32_t v = 0;
#pragma unroll
    for (int q = 0; q < 32; q++)
        v |= ((uint32_t)read_bool(x, base + q, mode)) << q;
    g_xpack[w] = v;
}

__global__ void prep_misc_kernel(const int* __restrict__ input_nodes,
                                 const void* __restrict__ init_res) {
    int i = blockIdx.x * blockDim.x + threadIdx.x;
    if (i >= RNODES) return;
    int mode = g_mode;
    int inv = -1;
#pragma unroll
    for (int q = 0; q < NIN; q++)
        if (input_nodes[q] == i) inv = q;
    g_inv[i] = inv;
    g_init[i] = read_bool(init_res, i, mode);
}

// Build pair-group combo table: entry (g, c-1, t) holds, for combo bits
// c = {bit0 -> k=2g, bit1 -> k=2g+1}, the packed sums for 4 nodes:
//   .x = u16(node t)    | u16(node t+128) << 16
//   .y = u16(node t+64) | u16(node t+192) << 16
__global__ void prep_tab_kernel(const void* __restrict__ W,
                                const int* __restrict__ primes) {
    int i = blockIdx.x * blockDim.x + threadIdx.x;
    if (i >= NGROUP * 3 * 64) return;
    int t   = i & 63;
    int cm1 = (i >> 6) % 3;
    int g   = i / (3 * 64);
    int c   = cm1 + 1;
    int k0 = 2 * g, k1 = 2 * g + 1;
    int mode = g_mode;
    uint32_t p0 = (c & 1) ? (uint32_t)primes[k0] : 0u;
    uint32_t p1 = (c & 2) ? (uint32_t)primes[k1] : 0u;
    uint32_t v[4];
#pragma unroll
    for (int q = 0; q < 4; q++) {
        int node = t + q * 64;
        uint32_t s = 0;
        if (read_bool(W, (long)node * RNODES + k0, mode)) s += p0;
        if (read_bool(W, (long)node * RNODES + k1, mode)) s += p1;
        v[q] = s;
    }
    uint2 e;
    e.x = v[0] | (v[2] << 16);   // t, t+128
    e.y = v[1] | (v[3] << 16);   // t+64, t+192
    g_tab[i] = e;
}

// 128 CTAs x 256 threads. CTA = 4 samples, 64 threads/sample (2 warps).
// Thread t owns nodes t, t+64, t+128, t+192 (two packed u16 accumulators).
__global__ void __launch_bounds__(256, 1)
reservoir_kernel(const float* __restrict__ roW,
                 const float* __restrict__ rob,
                 float* __restrict__ out) {
    extern __shared__ uint32_t sm[];
    uint32_t* sh_xw   = sm;                       // 2048 u32
    uint32_t* sh_r    = sm + 2048;                // 64 u32: 2 bufs * 4 samples * 8 words
    float*    sh_bits = (float*)(sm + 2112);      // 1024 floats (also safe underflow pad)
    uint2*    sh_tab  = (uint2*)(sm + 3136);      // 24576 uint2 = 192 KB

    const int tid  = threadIdx.x;
    const int sid  = tid >> 6;        // sample in CTA (0..3)
    const int t    = tid & 63;        // node-quad index
    const int ws   = (tid >> 5) & 1;  // warp within sample
    const int lane = tid & 31;

    for (int i = tid; i < NGROUP * 3 * 64; i += 256)
        sh_tab[i] = g_tab[i];
    for (int i = tid; i < 2048; i += 256)
        sh_xw[i] = g_xpack[blockIdx.x * 2048 + i];

    const int inv0 = g_inv[t];
    const int inv1 = g_inv[t + 64];
    const int inv2 = g_inv[t + 128];
    const int inv3 = g_inv[t + 192];
    unsigned b0 = (unsigned)g_init[t];
    unsigned b1 = (unsigned)g_init[t + 64];
    unsigned b2 = (unsigned)g_init[t + 128];
    unsigned b3 = (unsigned)g_init[t + 192];

    __syncthreads();

    const uint32_t* xs   = sh_xw + sid * NSTEP;
    const uint2*   tab_t = sh_tab + t;
    const int      barid = sid + 1;   // named barriers 1..4, keep 0 for syncthreads

    for (int s = 0; s < NSTEP; s++) {
        // 1) input override (applied before the matvec, as in the reference)
        uint32_t xw = xs[s];
        unsigned a0 = (inv0 >= 0) ? ((xw >> inv0) & 1u) : b0;
        unsigned a1 = (inv1 >= 0) ? ((xw >> inv1) & 1u) : b1;
        unsigned a2 = (inv2 >= 0) ? ((xw >> inv2) & 1u) : b2;
        unsigned a3 = (inv3 >= 0) ? ((xw >> inv3) & 1u) : b3;

        // 2) state bitmask words: node n -> word n>>5.
        unsigned m0 = __ballot_sync(0xffffffffu, a0);   // word ws
        unsigned m1 = __ballot_sync(0xffffffffu, a1);   // word ws+2
        unsigned m2 = __ballot_sync(0xffffffffu, a2);   // word ws+4
        unsigned m3 = __ballot_sync(0xffffffffu, a3);   // word ws+6
        uint32_t* rb = sh_r + ((s & 1) * 32) + sid * 8;
        if (lane == 0) {
            rb[ws]     = m0;
            rb[ws + 2] = m1;
            rb[ws + 4] = m2;
            rb[ws + 6] = m3;
        }
        asm volatile("bar.sync %0, 64;" :: "r"(barid) : "memory");

        uint4 ra  = *(const uint4*)(rb);
        uint4 rb4 = *(const uint4*)(rb + 4);
        uint32_t wv[8] = {ra.x, ra.y, ra.z, ra.w, rb4.x, rb4.y, rb4.z, rb4.w};

        // 3) pair-group combo sums, fully unrolled, branch-free
        uint32_t i0 = 0, i1 = 0, i2 = 0, i3 = 0;
#pragma unroll
        for (int w = 0; w < 8; w++) {
            uint32_t word = wv[w];
            uint32_t ax = 0, ay = 0;   // packed u16 pairs, per-word max < 65536
#pragma unroll
            for (int q = 0; q < 16; q++) {
                int g = w * 16 + q;
                uint32_t c = (word >> (2 * q)) & 3u;
                // c==0 address underflows into the pad region (never selected)
                uint2 e = tab_t[((g * 3 - 1) + (int)c) * 64];
                ax = c ? __vadd2(ax, e.x) : ax;
                ay = c ? __vadd2(ay, e.y) : ay;
            }
            i0 += ax & 0xFFFFu;
            i2 += ax >> 16;
            i1 += ay & 0xFFFFu;
            i3 += ay >> 16;
        }

        // 4) bit-packed LUT gather (8 MB, L2-resident)
        uint32_t w0 = g_lutbits[((uint32_t)t << 13)         + (i0 >> 5)];
        uint32_t w1 = g_lutbits[((uint32_t)(t + 64) << 13)  + (i1 >> 5)];
        uint32_t w2 = g_lutbits[((uint32_t)(t + 128) << 13) + (i2 >> 5)];
        uint32_t w3 = g_lutbits[((uint32_t)(t + 192) << 13) + (i3 >> 5)];
        b0 = (w0 >> (i0 & 31u)) & 1u;
        b1 = (w1 >> (i1 & 31u)) & 1u;
        b2 = (w2 >> (i2 & 31u)) & 1u;
        b3 = (w3 >> (i3 & 31u)) & 1u;
    }

    // Readout: out[m, o] = sum_j rf[m,j] * roW[o,j] + rob[o]
    float* bits = sh_bits + sid * 256;
    bits[t]       = (float)b0;
    bits[t + 64]  = (float)b1;
    bits[t + 128] = (float)b2;
    bits[t + 192] = (float)b3;
    __syncthreads();

    if (tid < 4 * NOUT) {
        int so = tid / NOUT;          // sample in CTA
        int o  = tid % NOUT;
        float acc = rob[o];
        const float* wrow = roW + o * RNODES;
        const float* bb = sh_bits + so * 256;
#pragma unroll 8
        for (int j = 0; j < RNODES; j++)
            acc += bb[j] * wrow[j];
        out[(blockIdx.x * 4 + so) * NOUT + o] = acc;
    }
}

extern "C" void kernel_launch(void* const* d_in, const int* in_sizes, int n_in,
                              void* d_out, int out_size) {
    const void* x       = d_in[0];                   // bool [512,512,4,8] (dtype-detected)
    const int*  innod   = (const int*)d_in[1];       // int32 [32]
    const int*  lut     = (const int*)d_in[2];       // int32 [256, 262144]
    const void* W       = d_in[3];                   // bool [256,256]
    const int*  primes  = (const int*)d_in[4];       // int32 [256]
    const void* initres = d_in[5];                   // bool [256]
    const float* roW    = (const float*)d_in[6];     // f32 [10,256]
    const float* rob    = (const float*)d_in[7];     // f32 [10]
    float* out = (float*)d_out;                      // f32 [512,10]

    cudaFuncSetAttribute(reservoir_kernel,
                         cudaFuncAttributeMaxDynamicSharedMemorySize, SMEM_BYTES);

    detect_kernel<<<1, 32>>>((const uint32_t*)x);
    pack_lut_kernel<<<(RNODES * LUT_WORDS + 255) / 256, 256>>>(lut);
    pack_x_kernel<<<(NSAMP * NSTEP + 255) / 256, 256>>>(x);
    prep_misc_kernel<<<1, 256>>>(innod, initres);
    prep_tab_kernel<<<(NGROUP * 3 * 64 + 255) / 256, 256>>>(W, primes);
    reservoir_kernel<<<128, 256, SMEM_BYTES>>>(roW, rob, out);
}